// round 8
// baseline (speedup 1.0000x reference)
#include <cuda_runtime.h>
#include <cuda_bf16.h>
#include <math.h>
#include <stdint.h>

#define S_LEN 4096
#define HIDDEN 2048
#define NH 8
#define NKV 4
#define HD 256

// ---------------- scratch (allocation-free device globals) -----------------
__device__ float g_q[(size_t)NH * S_LEN * HD];      // [h][s][d], tf32-rounded
__device__ float g_k[(size_t)NKV * S_LEN * HD];     // [h][s][d], tf32-rounded
__device__ float g_v[(size_t)NKV * S_LEN * HD];     // [h][s][d], tf32-rounded
__device__ float g_attn[(size_t)S_LEN * (NH * HD)]; // [s][h*HD+d], fp32
// int8 digit-split operands
__device__ int8_t g_a8h[(size_t)S_LEN * HIDDEN];    // A hi digit (hs, then attn)
__device__ int8_t g_a8l[(size_t)S_LEN * HIDDEN];    // A lo digit
__device__ float  g_as[S_LEN];                      // A row scales
__device__ int8_t g_wqh[(size_t)2048 * HIDDEN], g_wql[(size_t)2048 * HIDDEN];
__device__ int8_t g_wkh[(size_t)1024 * HIDDEN], g_wkl[(size_t)1024 * HIDDEN];
__device__ int8_t g_wvh[(size_t)1024 * HIDDEN], g_wvl[(size_t)1024 * HIDDEN];
__device__ int8_t g_woh[(size_t)2048 * HIDDEN], g_wol[(size_t)2048 * HIDDEN];
__device__ float  g_bsq[2048], g_bsk[1024], g_bsv[1024], g_bso[2048];
__device__ float  g_cmax[8 * 2048];                 // column-max partials

__device__ __forceinline__ float to_tf32(float x) {
    float r;
    asm("cvt.rna.tf32.f32 %0, %1;" : "=f"(r) : "f"(x));
    return r;
}

__device__ __forceinline__ uint32_t cvta_shared(const void* p) {
    uint32_t a;
    asm("{ .reg .u64 t; cvta.to.shared.u64 t, %1; cvt.u32.u64 %0, t; }"
        : "=r"(a) : "l"(p));
    return a;
}

__device__ __forceinline__ void cp16(uint32_t dst, const void* src) {
    asm volatile("cp.async.cg.shared.global [%0], [%1], 16;"
                 :: "r"(dst), "l"(src));
}
#define CP_COMMIT() asm volatile("cp.async.commit_group;")
#define CP_WAIT0()  asm volatile("cp.async.wait_group 0;")
#define CP_WAIT1()  asm volatile("cp.async.wait_group 1;")

#define MMA_TF32(C, A, B0, B1)                                              \
    asm volatile(                                                           \
        "mma.sync.aligned.m16n8k8.row.col.f32.tf32.tf32.f32 "               \
        "{%0,%1,%2,%3}, {%4,%5,%6,%7}, {%8,%9}, {%0,%1,%2,%3};"             \
        : "+f"((C)[0]), "+f"((C)[1]), "+f"((C)[2]), "+f"((C)[3])            \
        : "r"((A)[0]), "r"((A)[1]), "r"((A)[2]), "r"((A)[3]),               \
          "r"(B0), "r"(B1))

#define MMA_S8(C, A, B0, B1)                                                \
    asm volatile(                                                           \
        "mma.sync.aligned.m16n8k32.row.col.s32.s8.s8.s32 "                  \
        "{%0,%1,%2,%3}, {%4,%5,%6,%7}, {%8,%9}, {%0,%1,%2,%3};"             \
        : "+r"((C)[0]), "+r"((C)[1]), "+r"((C)[2]), "+r"((C)[3])            \
        : "r"((A)[0]), "r"((A)[1]), "r"((A)[2]), "r"((A)[3]),               \
          "r"(B0), "r"(B1))

// q in [-32512, 32512] -> hi digit [-127,127], lo digit [-128,127]
__device__ __forceinline__ void digit_split(float v, float inv, int8_t& h, int8_t& l) {
    int q = __float2int_rn(v * inv);
    q = max(-32512, min(32512, q));
    int hi = (q + 128) >> 8;
    h = (int8_t)hi;
    l = (int8_t)(q - (hi << 8));
}

// ---------------------------------------------------------------------------
// Row quantize: src [rows, 2048] fp32 -> hi/lo s8 planes + per-row scale.
// One block per row, 256 threads x 8 elements.
// ---------------------------------------------------------------------------
__global__ __launch_bounds__(256) void rowquant_kernel(
    const float* __restrict__ src, int8_t* __restrict__ hi,
    int8_t* __restrict__ lo, float* __restrict__ scale)
{
    const int row = blockIdx.x;
    const int tid = threadIdx.x;
    const float4* s4 = (const float4*)(src + (size_t)row * 2048);
    float4 v0 = s4[tid * 2], v1 = s4[tid * 2 + 1];
    float f[8] = {v0.x, v0.y, v0.z, v0.w, v1.x, v1.y, v1.z, v1.w};

    float mx = 0.f;
#pragma unroll
    for (int j = 0; j < 8; j++) mx = fmaxf(mx, fabsf(f[j]));
#pragma unroll
    for (int off = 16; off > 0; off >>= 1)
        mx = fmaxf(mx, __shfl_xor_sync(0xffffffffu, mx, off));
    __shared__ float red[8], bcast;
    if ((tid & 31) == 0) red[tid >> 5] = mx;
    __syncthreads();
    if (tid == 0) {
        float m = 1e-20f;
#pragma unroll
        for (int w = 0; w < 8; w++) m = fmaxf(m, red[w]);
        bcast = 32512.f / m;
        scale[row] = m / 32512.f;
    }
    __syncthreads();
    float inv = bcast;

    uint64_t ph = 0, pl = 0;
#pragma unroll
    for (int j = 0; j < 8; j++) {
        int8_t h, l;
        digit_split(f[j], inv, h, l);
        ph |= (uint64_t)(uint8_t)h << (8 * j);
        pl |= (uint64_t)(uint8_t)l << (8 * j);
    }
    ((uint64_t*)(hi + (size_t)row * 2048))[tid] = ph;
    ((uint64_t*)(lo + (size_t)row * 2048))[tid] = pl;
}

// ---------------------------------------------------------------------------
// Column-max partials: W [2048, N] -> partial[seg][n] over 256-row segments.
// ---------------------------------------------------------------------------
__global__ void colmax_kernel(const float* __restrict__ W,
                              float* __restrict__ partial, int N)
{
    const int n = blockIdx.x * 256 + threadIdx.x;
    const int seg = blockIdx.y;
    float m = 0.f;
    for (int r = seg * 256; r < seg * 256 + 256; r++)
        m = fmaxf(m, fabsf(W[(size_t)r * N + n]));
    partial[seg * N + n] = m;
}

// ---------------------------------------------------------------------------
// Transpose + quantize: W [2048, N] fp32 -> Bh/Bl [N, 2048] s8 + b_s[N].
// Block (32,8) on a 32k x 32n tile.
// ---------------------------------------------------------------------------
__global__ void tquant_kernel(const float* __restrict__ W,
                              const float* __restrict__ partial,
                              int8_t* __restrict__ bh, int8_t* __restrict__ bl,
                              float* __restrict__ bs, int N)
{
    __shared__ float t[32][33];
    __shared__ float cinv[32];
    const int n0 = blockIdx.x * 32, k0 = blockIdx.y * 32;
    const int tx = threadIdx.x, ty = threadIdx.y;

    if (ty == 0) {
        float m = 1e-20f;
#pragma unroll
        for (int s = 0; s < 8; s++) m = fmaxf(m, partial[s * N + n0 + tx]);
        cinv[tx] = 32512.f / m;
        if (blockIdx.y == 0) bs[n0 + tx] = m / 32512.f;
    }
#pragma unroll
    for (int j = 0; j < 4; j++)
        t[ty + 8 * j][tx] = W[(size_t)(k0 + ty + 8 * j) * N + n0 + tx];
    __syncthreads();

    const int nl = ty * 4 + (tx >> 3);
    const int kl = (tx & 7) * 4;
    const float inv = cinv[nl];
    uint32_t ph = 0, pl = 0;
#pragma unroll
    for (int i = 0; i < 4; i++) {
        int8_t h, l;
        digit_split(t[kl + i][nl], inv, h, l);
        ph |= (uint32_t)(uint8_t)h << (8 * i);
        pl |= (uint32_t)(uint8_t)l << (8 * i);
    }
    *(uint32_t*)&bh[(size_t)(n0 + nl) * 2048 + k0 + kl] = ph;
    *(uint32_t*)&bl[(size_t)(n0 + nl) * 2048 + k0 + kl] = pl;
}

// ---------------------------------------------------------------------------
// INT8 digit-split GEMM: C[M,N] = A[M,2048] @ B[N,2048]^T.
// C = as[m]*bs[n]*(65536*AhBh + 256*(AhBl+AlBh)); AlBl dropped (~2^-16).
// 128x128 CTA tile, k-chunk 64, 512 threads = 16 warps (4m x 4n), warp 32x32,
// m16n8k32 s8 IMMA, cp.async double-buffered.
// merged=1: fused QKV, region by bn (q:0-2047, k:2048-3071, v:3072-4095),
//           headed [head][m][d] output, tf32-rounded.
// ---------------------------------------------------------------------------
#define GI_PLANE 10240                  // 128 rows * 80 B (64 data + 16 pad)
#define GI_STAGE (4 * GI_PLANE)         // Ah, Al, Bh, Bl
#define GI_SMEM  (2 * GI_STAGE)         // 81920 B

__global__ __launch_bounds__(512, 1) void gemm_i8_kernel(
    const int8_t* __restrict__ Ah, const int8_t* __restrict__ Al,
    const float* __restrict__ as_,
    const int8_t* __restrict__ Bh0, const int8_t* __restrict__ Bl0,
    const float* __restrict__ bs0,
    const int8_t* __restrict__ Bh1, const int8_t* __restrict__ Bl1,
    const float* __restrict__ bs1,
    const int8_t* __restrict__ Bh2, const int8_t* __restrict__ Bl2,
    const float* __restrict__ bs2,
    float* __restrict__ Cq, float* __restrict__ Ck, float* __restrict__ Cv,
    float* __restrict__ Cplain, int M, int merged)
{
    extern __shared__ char gsm[];
    const uint32_t smem_base = cvta_shared(gsm);

    const int tid  = threadIdx.x;
    const int lane = tid & 31;
    const int wid  = tid >> 5;
    const int wm   = (wid & 3) * 32;
    const int wn   = (wid >> 2) * 32;
    const int bm   = blockIdx.y * 128;
    const int bn   = blockIdx.x * 128;
    const int grp  = lane >> 2;
    const int qd   = lane & 3;

    const int8_t *Bh, *Bl;
    const float* bsp;
    float* Cp = Cplain;
    int nb, head = 0, colb0 = 0;
    if (merged) {
        if (bn < 2048)      { Bh = Bh0; Bl = Bl0; bsp = bs0; Cp = Cq; nb = bn; }
        else if (bn < 3072) { Bh = Bh1; Bl = Bl1; bsp = bs1; Cp = Ck; nb = bn - 2048; }
        else                { Bh = Bh2; Bl = Bl2; bsp = bs2; Cp = Cv; nb = bn - 3072; }
        head = nb >> 8;
        colb0 = nb & 255;
    } else {
        Bh = Bh0; Bl = Bl0; bsp = bs0; nb = bn;
    }

    const int rowL = tid >> 2;          // 0..127
    const int c16  = tid & 3;           // 16B group within 64B row

    auto load_stage = [&](int chunk, int st) {
        const int k0 = chunk * 64;
        const uint32_t sb = smem_base + st * GI_STAGE;
        const uint32_t off = rowL * 80 + c16 * 16;
        cp16(sb + off,                &Ah[(size_t)(bm + rowL) * 2048 + k0 + c16 * 16]);
        cp16(sb + GI_PLANE + off,     &Al[(size_t)(bm + rowL) * 2048 + k0 + c16 * 16]);
        cp16(sb + 2 * GI_PLANE + off, &Bh[(size_t)(nb + rowL) * 2048 + k0 + c16 * 16]);
        cp16(sb + 3 * GI_PLANE + off, &Bl[(size_t)(nb + rowL) * 2048 + k0 + c16 * 16]);
        CP_COMMIT();
    };

    int c1[2][4][4], c2[2][4][4];
#pragma unroll
    for (int mf = 0; mf < 2; mf++)
#pragma unroll
        for (int nt = 0; nt < 4; nt++)
#pragma unroll
            for (int r = 0; r < 4; r++) { c1[mf][nt][r] = 0; c2[mf][nt][r] = 0; }

    load_stage(0, 0);

    for (int i = 0; i < 32; i++) {
        const int st = i & 1;
        CP_WAIT0();
        __syncthreads();
        if (i + 1 < 32) load_stage(i + 1, st ^ 1);

        const uint32_t* ps  = (const uint32_t*)(gsm + st * GI_STAGE);
        const uint32_t* pAh = ps;
        const uint32_t* pAl = ps + 2560;
        const uint32_t* pBh = ps + 5120;
        const uint32_t* pBl = ps + 7680;

#pragma unroll
        for (int s = 0; s < 2; s++) {
            const int wq = s * 8 + qd;
            uint32_t ah[2][4], al[2][4];
#pragma unroll
            for (int mf = 0; mf < 2; mf++) {
                const int R = wm + mf * 16 + grp;
                ah[mf][0] = pAh[R * 20 + wq];
                ah[mf][1] = pAh[(R + 8) * 20 + wq];
                ah[mf][2] = pAh[R * 20 + wq + 4];
                ah[mf][3] = pAh[(R + 8) * 20 + wq + 4];
                al[mf][0] = pAl[R * 20 + wq];
                al[mf][1] = pAl[(R + 8) * 20 + wq];
                al[mf][2] = pAl[R * 20 + wq + 4];
                al[mf][3] = pAl[(R + 8) * 20 + wq + 4];
            }
#pragma unroll
            for (int nt = 0; nt < 4; nt++) {
                const int n = wn + nt * 8 + grp;
                uint32_t bh0 = pBh[n * 20 + wq];
                uint32_t bh1 = pBh[n * 20 + wq + 4];
                uint32_t bl0 = pBl[n * 20 + wq];
                uint32_t bl1 = pBl[n * 20 + wq + 4];
#pragma unroll
                for (int mf = 0; mf < 2; mf++) {
                    MMA_S8(c1[mf][nt], ah[mf], bh0, bh1);
                    MMA_S8(c2[mf][nt], ah[mf], bl0, bl1);
                    MMA_S8(c2[mf][nt], al[mf], bh0, bh1);
                }
            }
        }
        __syncthreads();
    }

    // epilogue: merge digits, apply scales
    const int m0 = bm + wm + grp;
#pragma unroll
    for (int mf = 0; mf < 2; mf++) {
        const int m = m0 + mf * 16;
        const float as0 = as_[m];
        const float as1 = as_[m + 8];
#pragma unroll
        for (int nt = 0; nt < 4; nt++) {
            const int ncol = wn + nt * 8 + 2 * qd;
            const float bv0 = bsp[nb + ncol];
            const float bv1 = bsp[nb + ncol + 1];
            float f00 = as0 * bv0 * (65536.f * (float)c1[mf][nt][0] + 256.f * (float)c2[mf][nt][0]);
            float f01 = as0 * bv1 * (65536.f * (float)c1[mf][nt][1] + 256.f * (float)c2[mf][nt][1]);
            float f10 = as1 * bv0 * (65536.f * (float)c1[mf][nt][2] + 256.f * (float)c2[mf][nt][2]);
            float f11 = as1 * bv1 * (65536.f * (float)c1[mf][nt][3] + 256.f * (float)c2[mf][nt][3]);
            if (merged) {
                size_t base = (size_t)head * ((size_t)M * HD) + colb0 + ncol;
                *(float2*)&Cp[base + (size_t)m * HD] =
                    make_float2(to_tf32(f00), to_tf32(f01));
                *(float2*)&Cp[base + (size_t)(m + 8) * HD] =
                    make_float2(to_tf32(f10), to_tf32(f11));
            } else {
                *(float2*)&Cplain[(size_t)m * 2048 + bn + ncol] = make_float2(f00, f01);
                *(float2*)&Cplain[(size_t)(m + 8) * 2048 + bn + ncol] = make_float2(f10, f11);
            }
        }
    }
}

// ---------------------------------------------------------------------------
// RoPE: one thread per (s, i); cos/sin once (fp64 range reduction), applied
// to all 12 heads. Folds SCALING=0.0625 into q. tf32-rounds outputs.
// position_ids int32/int64 auto-detected via word[1].
// ---------------------------------------------------------------------------
__global__ void rope_kernel(const void* __restrict__ pos_raw)
{
    int idx = blockIdx.x * blockDim.x + threadIdx.x;
    if (idx >= S_LEN * 128) return;
    int i = idx & 127;
    int s = idx >> 7;

    const int* p32 = (const int*)pos_raw;
    long long pll = (p32[1] == 0) ? ((const long long*)pos_raw)[s]
                                  : (long long)p32[s];
    float p = (float)pll;

    double invd = exp(-(double)i * (9.210340371976184 / 128.0));
    float f = (float)((double)p * invd);
    const double TWO_PI = 6.283185307179586476925287;
    double r = (double)f;
    r -= TWO_PI * floor(r / TWO_PI);
    float sv = sinf((float)r);
    float cv = cosf((float)r);

#pragma unroll
    for (int h = 0; h < NH; h++) {
        float* base = g_q + ((size_t)h * S_LEN + s) * HD;
        float x1 = base[i], x2 = base[i + 128];
        base[i]       = to_tf32((x1 * cv - x2 * sv) * 0.0625f);
        base[i + 128] = to_tf32((x2 * cv + x1 * sv) * 0.0625f);
    }
#pragma unroll
    for (int h = 0; h < NKV; h++) {
        float* base = g_k + ((size_t)h * S_LEN + s) * HD;
        float x1 = base[i], x2 = base[i + 128];
        base[i]       = to_tf32(x1 * cv - x2 * sv);
        base[i + 128] = to_tf32(x2 * cv + x1 * sv);
    }
}

// ---------------------------------------------------------------------------
// Tensor-core flash attention (tf32 mma.sync) with tanh softcap — as R7.
// Epilogue now writes plain fp32 (O-proj quantizes from fp32).
// ---------------------------------------------------------------------------
#define QK_STRIDE 268
#define V_STRIDE  264
#define S_STRIDE  68
#define OFF_QF 0
#define OFF_KF (64 * QK_STRIDE)
#define OFF_SS (OFF_KF + 64 * QK_STRIDE)
#define OFF_VS (OFF_SS + 64 * S_STRIDE)
#define OFF_RS (OFF_VS + 64 * V_STRIDE)
#define OFF_LI (OFF_RS + 64)
#define ATTN_SMEM_FLOATS (OFF_LI + 64)

__global__ __launch_bounds__(256) void attn_mma_kernel()
{
    extern __shared__ float sm[];
    float* Qf = sm + OFF_QF;
    float* Ss = sm + OFF_SS;
    float* rs = sm + OFF_RS;
    float* li = sm + OFF_LI;
    const uint32_t* Qfu = (const uint32_t*)Qf;
    const uint32_t* Kfu = (const uint32_t*)(sm + OFF_KF);
    const uint32_t* Ssu = (const uint32_t*)Ss;
    const uint32_t* Vsu = (const uint32_t*)(sm + OFF_VS);
    const uint32_t smem_base = cvta_shared(sm);
    const uint32_t kf_base = smem_base + OFF_KF * 4;
    const uint32_t vs_base = smem_base + OFF_VS * 4;

    const int h  = blockIdx.y;
    const int hk = h >> 1;
    const int tid  = threadIdx.x;
    const int lane = tid & 31;
    const int wid  = tid >> 5;
    const int wr   = wid & 3;
    const int wc   = wid >> 2;
    const int grp  = lane >> 2;
    const int qd   = lane & 3;
    const int r0   = wr * 16 + grp;
    const int ty   = tid >> 4;
    const int tx   = tid & 15;

    const float* Qh = g_q + (size_t)h  * S_LEN * HD;
    const float* Kh = g_k + (size_t)hk * S_LEN * HD;
    const float* Vh = g_v + (size_t)hk * S_LEN * HD;

    const float LOG2E = 1.4426950408889634f;

    for (int half = 0; half < 2; half++) {
        const int qt = half ? (63 - blockIdx.x) : blockIdx.x;
        const int q0 = qt * 64;

        __syncthreads();
#pragma unroll
        for (int p = 0; p < 16; p++) {
            int idx = tid + p * 256;
            int row = idx >> 6, c4 = idx & 63;
            *(float4*)&Qf[row * QK_STRIDE + c4 * 4] =
                *(const float4*)&Qh[(size_t)(q0 + row) * HD + c4 * 4];
        }

        float m[4], l[4], o[16][4];
#pragma unroll
        for (int r = 0; r < 4; r++) { m[r] = -3.0e38f; l[r] = 0.f; }
#pragma unroll
        for (int nt = 0; nt < 16; nt++)
#pragma unroll
            for (int r = 0; r < 4; r++) o[nt][r] = 0.f;

        for (int kb = 0; kb <= qt; kb++) {
            const int k0 = kb * 64;
            __syncthreads();
#pragma unroll
            for (int p = 0; p < 16; p++) {
                int idx = tid + p * 256;
                int row = idx >> 6, c4 = idx & 63;
                cp16(kf_base + row * (QK_STRIDE * 4) + c4 * 16,
                     &Kh[(size_t)(k0 + row) * HD + c4 * 4]);
            }
            CP_COMMIT();
#pragma unroll
            for (int p = 0; p < 16; p++) {
                int idx = tid + p * 256;
                int row = idx >> 6, c4 = idx & 63;
                cp16(vs_base + row * (V_STRIDE * 4) + c4 * 16,
                     &Vh[(size_t)(k0 + row) * HD + c4 * 4]);
            }
            CP_COMMIT();
            CP_WAIT1();
            __syncthreads();

            float s[4][4];
#pragma unroll
            for (int nt = 0; nt < 4; nt++)
#pragma unroll
                for (int r = 0; r < 4; r++) s[nt][r] = 0.f;
#pragma unroll 8
            for (int ks = 0; ks < 32; ks++) {
                const int kc = ks * 8 + qd;
                uint32_t a[4];
                a[0] = Qfu[r0 * QK_STRIDE + kc];
                a[1] = Qfu[(r0 + 8) * QK_STRIDE + kc];
                a[2] = Qfu[r0 * QK_STRIDE + kc + 4];
                a[3] = Qfu[(r0 + 8) * QK_STRIDE + kc + 4];
#pragma unroll
                for (int nt = 0; nt < 4; nt++) {
                    int nc = wc * 32 + nt * 8 + grp;
                    uint32_t b0 = Kfu[nc * QK_STRIDE + kc];
                    uint32_t b1 = Kfu[nc * QK_STRIDE + kc + 4];
                    MMA_TF32(s[nt], a, b0, b1);
                }
            }
#pragma unroll
            for (int nt = 0; nt < 4; nt++) {
                int col = wc * 32 + nt * 8 + 2 * qd;
                *(float2*)&Ss[r0 * S_STRIDE + col] = make_float2(s[nt][0], s[nt][1]);
                *(float2*)&Ss[(r0 + 8) * S_STRIDE + col] = make_float2(s[nt][2], s[nt][3]);
            }
            CP_WAIT0();
            __syncthreads();

#pragma unroll
            for (int r = 0; r < 4; r++) {
                const int row = ty * 4 + r;
                const int qrow = q0 + row;
                float4 raw = *(float4*)&Ss[row * S_STRIDE + tx * 4];
                float sv[4] = {raw.x, raw.y, raw.z, raw.w};
#pragma unroll
                for (int cc = 0; cc < 4; cc++) {
                    float x = sv[cc];
                    float u = x * 0.02f;
                    float u2 = u * u;
                    float val = x * (1.f + u2 * (-0.333333333f +
                                  u2 * (0.133333333f + u2 * -0.053968254f)));
                    if (u2 > 0.1225f) val = 50.f * tanhf(u);
                    int kcol = k0 + tx * 4 + cc;
                    if (kcol > qrow) val = -1.0e30f;
                    sv[cc] = val;
                }
                float mx = fmaxf(fmaxf(sv[0], sv[1]), fmaxf(sv[2], sv[3]));
#pragma unroll
                for (int off = 1; off < 16; off <<= 1)
                    mx = fmaxf(mx, __shfl_xor_sync(0xffffffffu, mx, off));
                float mn = fmaxf(m[r], mx);
                float rescale = exp2f((m[r] - mn) * LOG2E);
                float4 pw;
                pw.x = to_tf32(exp2f((sv[0] - mn) * LOG2E));
                pw.y = to_tf32(exp2f((sv[1] - mn) * LOG2E));
                pw.z = to_tf32(exp2f((sv[2] - mn) * LOG2E));
                pw.w = to_tf32(exp2f((sv[3] - mn) * LOG2E));
                float psum = (pw.x + pw.y) + (pw.z + pw.w);
                *(float4*)&Ss[row * S_STRIDE + tx * 4] = pw;
#pragma unroll
                for (int off = 1; off < 16; off <<= 1)
                    psum += __shfl_xor_sync(0xffffffffu, psum, off);
                l[r] = l[r] * rescale + psum;
                m[r] = mn;
                if (tx == 0) rs[row] = rescale;
            }
            __syncthreads();

            float rc0 = rs[r0], rc1 = rs[r0 + 8];
#pragma unroll
            for (int nt = 0; nt < 16; nt++) {
                o[nt][0] *= rc0; o[nt][1] *= rc0;
                o[nt][2] *= rc1; o[nt][3] *= rc1;
            }
#pragma unroll
            for (int ks = 0; ks < 8; ks++) {
                const int kc = ks * 8 + qd;
                uint32_t a[4];
                a[0] = Ssu[r0 * S_STRIDE + kc];
                a[1] = Ssu[(r0 + 8) * S_STRIDE + kc];
                a[2] = Ssu[r0 * S_STRIDE + kc + 4];
                a[3] = Ssu[(r0 + 8) * S_STRIDE + kc + 4];
#pragma unroll
                for (int nt = 0; nt < 16; nt++) {
                    int nc = wc * 128 + nt * 8 + grp;
                    uint32_t b0 = Vsu[kc * V_STRIDE + nc];
                    uint32_t b1 = Vsu[(kc + 4) * V_STRIDE + nc];
                    MMA_TF32(o[nt], a, b0, b1);
                }
            }
        }

        if (tx == 0) {
#pragma unroll
            for (int r = 0; r < 4; r++) li[ty * 4 + r] = 1.f / l[r];
        }
        __syncthreads();
        float li0 = li[r0], li1 = li[r0 + 8];
#pragma unroll
        for (int nt = 0; nt < 16; nt++) {
            int col = h * HD + wc * 128 + nt * 8 + 2 * qd;
            *(float2*)&g_attn[(size_t)(q0 + r0) * (NH * HD) + col] =
                make_float2(o[nt][0] * li0, o[nt][1] * li0);
            *(float2*)&g_attn[(size_t)(q0 + r0 + 8) * (NH * HD) + col] =
                make_float2(o[nt][2] * li1, o[nt][3] * li1);
        }
    }
}

// ---------------------------------------------------------------------------
extern "C" void kernel_launch(void* const* d_in, const int* in_sizes, int n_in,
                              void* d_out, int out_size)
{
    const float* hs  = (const float*)d_in[0];
    // d_in[1] = attention_mask: pure causal (window >= S), recomputed in-kernel
    const void*  pos = d_in[2];
    const float* wq  = (const float*)d_in[3];
    const float* wk  = (const float*)d_in[4];
    const float* wv  = (const float*)d_in[5];
    const float* wo  = (const float*)d_in[6];
    float* out = (float*)d_out;

    float *pq, *pk, *pv, *pa, *pas, *pbsq, *pbsk, *pbsv, *pbso, *pcm;
    int8_t *a8h, *a8l, *wqh, *wql, *wkh, *wkl, *wvh, *wvl, *woh, *wol;
    cudaGetSymbolAddress((void**)&pq,   g_q);
    cudaGetSymbolAddress((void**)&pk,   g_k);
    cudaGetSymbolAddress((void**)&pv,   g_v);
    cudaGetSymbolAddress((void**)&pa,   g_attn);
    cudaGetSymbolAddress((void**)&pas,  g_as);
    cudaGetSymbolAddress((void**)&pbsq, g_bsq);
    cudaGetSymbolAddress((void**)&pbsk, g_bsk);
    cudaGetSymbolAddress((void**)&pbsv, g_bsv);
    cudaGetSymbolAddress((void**)&pbso, g_bso);
    cudaGetSymbolAddress((void**)&pcm,  g_cmax);
    cudaGetSymbolAddress((void**)&a8h,  g_a8h);
    cudaGetSymbolAddress((void**)&a8l,  g_a8l);
    cudaGetSymbolAddress((void**)&wqh,  g_wqh);
    cudaGetSymbolAddress((void**)&wql,  g_wql);
    cudaGetSymbolAddress((void**)&wkh,  g_wkh);
    cudaGetSymbolAddress((void**)&wkl,  g_wkl);
    cudaGetSymbolAddress((void**)&wvh,  g_wvh);
    cudaGetSymbolAddress((void**)&wvl,  g_wvl);
    cudaGetSymbolAddress((void**)&woh,  g_woh);
    cudaGetSymbolAddress((void**)&wol,  g_wol);

    cudaFuncSetAttribute(gemm_i8_kernel,
                         cudaFuncAttributeMaxDynamicSharedMemorySize, GI_SMEM);
    const int attn_smem = ATTN_SMEM_FLOATS * 4;
    cudaFuncSetAttribute(attn_mma_kernel,
                         cudaFuncAttributeMaxDynamicSharedMemorySize, attn_smem);

    dim3 tqb(32, 8);
    // quantize activations + weights
    rowquant_kernel<<<S_LEN, 256>>>(hs, a8h, a8l, pas);
    colmax_kernel<<<dim3(8, 8), 256>>>(wq, pcm, 2048);
    tquant_kernel<<<dim3(64, 64), tqb>>>(wq, pcm, wqh, wql, pbsq, 2048);
    colmax_kernel<<<dim3(4, 8), 256>>>(wk, pcm, 1024);
    tquant_kernel<<<dim3(32, 64), tqb>>>(wk, pcm, wkh, wkl, pbsk, 1024);
    colmax_kernel<<<dim3(4, 8), 256>>>(wv, pcm, 1024);
    tquant_kernel<<<dim3(32, 64), tqb>>>(wv, pcm, wvh, wvl, pbsv, 1024);
    colmax_kernel<<<dim3(8, 8), 256>>>(wo, pcm, 2048);
    tquant_kernel<<<dim3(64, 64), tqb>>>(wo, pcm, woh, wol, pbso, 2048);

    // fused QKV projection (int8 digit-split IMMA)
    gemm_i8_kernel<<<dim3(32, 32), 512, GI_SMEM>>>(
        a8h, a8l, pas, wqh, wql, pbsq, wkh, wkl, pbsk, wvh, wvl, pbsv,
        pq, pk, pv, nullptr, S_LEN, 1);
    // RoPE (+ fold attention scaling into q)
    rope_kernel<<<(S_LEN * 128) / 256, 256>>>(pos);
    // causal flash attention with tanh softcap (tf32)
    attn_mma_kernel<<<dim3(32, NH), 256, attn_smem>>>();
    // output projection: quantize attn output, int8 GEMM -> out
    rowquant_kernel<<<S_LEN, 256>>>(pa, a8h, a8l, pas);
    gemm_i8_kernel<<<dim3(16, 32), 512, GI_SMEM>>>(
        a8h, a8l, pas, woh, wol, pbso, nullptr, nullptr, nullptr,
        nullptr, nullptr, nullptr, nullptr, nullptr, nullptr, out, S_LEN, 0);
}

// round 9
// speedup vs baseline: 4.0180x; 4.0180x over previous
#include <cuda_runtime.h>
#include <cuda_fp16.h>
#include <math.h>
#include <stdint.h>

#define S_LEN 4096
#define NH 8
#define NKV 4
#define HD 256

// ---------------- scratch (allocation-free device globals) -----------------
__device__ __half g_q[(size_t)NH * S_LEN * HD];     // [h][s][d] fp16
__device__ __half g_k[(size_t)NKV * S_LEN * HD];    // [h][s][d] fp16
__device__ __half g_vt[(size_t)NKV * HD * S_LEN];   // [h][d][s] fp16 (transposed)
__device__ float  g_attn[(size_t)S_LEN * 2048];     // [s][h*HD+d] fp32
__device__ __half g_ah[(size_t)S_LEN * 2048];       // A fp16 (hs, then attn)
__device__ __half g_wqt[(size_t)2048 * 2048];       // weights [N][K] fp16
__device__ __half g_wkt[(size_t)1024 * 2048];
__device__ __half g_wvt[(size_t)1024 * 2048];
__device__ __half g_wot[(size_t)2048 * 2048];

__device__ __forceinline__ uint32_t cvta_shared(const void* p) {
    uint32_t a;
    asm("{ .reg .u64 t; cvta.to.shared.u64 t, %1; cvt.u32.u64 %0, t; }"
        : "=r"(a) : "l"(p));
    return a;
}

__device__ __forceinline__ void cp16(uint32_t dst, const void* src) {
    asm volatile("cp.async.cg.shared.global [%0], [%1], 16;"
                 :: "r"(dst), "l"(src));
}
#define CP_COMMIT() asm volatile("cp.async.commit_group;")
#define CP_WAIT0()  asm volatile("cp.async.wait_group 0;")
#define CP_WAIT1()  asm volatile("cp.async.wait_group 1;")

#define MMA_F16(C, A, B0, B1)                                               \
    asm volatile(                                                           \
        "mma.sync.aligned.m16n8k16.row.col.f32.f16.f16.f32 "                \
        "{%0,%1,%2,%3}, {%4,%5,%6,%7}, {%8,%9}, {%0,%1,%2,%3};"             \
        : "+f"((C)[0]), "+f"((C)[1]), "+f"((C)[2]), "+f"((C)[3])            \
        : "r"((A)[0]), "r"((A)[1]), "r"((A)[2]), "r"((A)[3]),               \
          "r"(B0), "r"(B1))

__device__ __forceinline__ uint32_t pack2(float a, float b) {
    __half2 h = __floats2half2_rn(a, b);
    return *(uint32_t*)&h;
}

// ---------------------------------------------------------------------------
// Prepass: fp32 -> fp16 (rn), 8 elems/thread.
// ---------------------------------------------------------------------------
__global__ void tohalf_kernel(const float* __restrict__ src,
                              __half* __restrict__ dst, int n8)
{
    int i = blockIdx.x * blockDim.x + threadIdx.x;
    if (i >= n8) return;
    float4 a = ((const float4*)src)[i * 2];
    float4 b = ((const float4*)src)[i * 2 + 1];
    uint4 o;
    o.x = pack2(a.x, a.y); o.y = pack2(a.z, a.w);
    o.z = pack2(b.x, b.y); o.w = pack2(b.z, b.w);
    ((uint4*)dst)[i] = o;
}

// ---------------------------------------------------------------------------
// Prepass: transpose W [2048, N] fp32 -> Wt [N, 2048] fp16.
// ---------------------------------------------------------------------------
__global__ void thalf_kernel(const float* __restrict__ W,
                             __half* __restrict__ Wt, int N)
{
    __shared__ float t[32][33];
    const int n0 = blockIdx.x * 32, k0 = blockIdx.y * 32;
    const int tx = threadIdx.x, ty = threadIdx.y;
#pragma unroll
    for (int j = 0; j < 4; j++)
        t[ty + 8 * j][tx] = W[(size_t)(k0 + ty + 8 * j) * N + n0 + tx];
    __syncthreads();
    const int nl = ty * 4 + (tx >> 3);
    const int kl = (tx & 7) * 4;
    uint2 o;
    o.x = pack2(t[kl + 0][nl], t[kl + 1][nl]);
    o.y = pack2(t[kl + 2][nl], t[kl + 3][nl]);
    *(uint2*)&Wt[(size_t)(n0 + nl) * 2048 + k0 + kl] = o;
}

// ---------------------------------------------------------------------------
// fp16 tensor-core GEMM: C[M,N] = A[M,2048] @ Wt[N,2048]^T, m16n8k16,
// 128x128 CTA tile, BK=64, 8 warps (4m x 2n), cp.async double-buffered.
// merged=1: fused QKV. bn<2048 -> q (fp16 headed [h][s][d]);
//   <3072 -> k (same); else v, written TRANSPOSED [h][d][s] fp16.
// merged=0: plain fp32 out [M,2048].
// ---------------------------------------------------------------------------
#define GH_PLANE 18432                   // 128 rows * 144 B
#define GH_STAGE (2 * GH_PLANE)
#define GH_SMEM  (2 * GH_STAGE)          // 73728 B

__global__ __launch_bounds__(256, 2) void gemm_h_kernel(
    const __half* __restrict__ A,
    const __half* __restrict__ B0t, const __half* __restrict__ B1t,
    const __half* __restrict__ B2t,
    __half* __restrict__ Cq, __half* __restrict__ Ck, __half* __restrict__ Cvt,
    float* __restrict__ Cplain, int merged)
{
    extern __shared__ char gsm[];
    const uint32_t smem_base = cvta_shared(gsm);

    const int tid  = threadIdx.x;
    const int lane = tid & 31;
    const int wid  = tid >> 5;
    const int wm   = (wid & 3) * 32;
    const int wn   = (wid >> 2) * 64;
    const int bm   = blockIdx.y * 128;
    const int bn   = blockIdx.x * 128;
    const int grp  = lane >> 2;
    const int qd   = lane & 3;

    const __half* Bt;
    int nb, head = 0, colb0 = 0, region = 0;
    if (merged) {
        if (bn < 2048)      { Bt = B0t; nb = bn;        region = 0; }
        else if (bn < 3072) { Bt = B1t; nb = bn - 2048; region = 1; }
        else                { Bt = B2t; nb = bn - 3072; region = 2; }
        head = nb >> 8;
        colb0 = nb & 255;
    } else {
        Bt = B0t; nb = bn;
    }

    auto load_stage = [&](int chunk, int st) {
        const int k0 = chunk * 64;
        const uint32_t sb = smem_base + st * GH_STAGE;
#pragma unroll
        for (int p = 0; p < 4; p++) {
            int idx = tid + p * 256;
            int row = idx >> 3, c = idx & 7;
            cp16(sb + row * 144 + c * 16,
                 &A[(size_t)(bm + row) * 2048 + k0 + c * 8]);
            cp16(sb + GH_PLANE + row * 144 + c * 16,
                 &Bt[(size_t)(nb + row) * 2048 + k0 + c * 8]);
        }
        CP_COMMIT();
    };

    float c[2][8][4];
#pragma unroll
    for (int mf = 0; mf < 2; mf++)
#pragma unroll
        for (int nt = 0; nt < 8; nt++)
#pragma unroll
            for (int r = 0; r < 4; r++) c[mf][nt][r] = 0.f;

    load_stage(0, 0);

    for (int i = 0; i < 32; i++) {
        const int st = i & 1;
        CP_WAIT0();
        __syncthreads();
        if (i + 1 < 32) load_stage(i + 1, st ^ 1);

        const uint32_t* Asu = (const uint32_t*)(gsm + st * GH_STAGE);
        const uint32_t* Bsu = (const uint32_t*)(gsm + st * GH_STAGE + GH_PLANE);
#pragma unroll
        for (int s = 0; s < 4; s++) {
            const int kc = s * 8 + qd;
            uint32_t a[2][4];
#pragma unroll
            for (int mf = 0; mf < 2; mf++) {
                const int R = wm + mf * 16 + grp;
                a[mf][0] = Asu[R * 36 + kc];
                a[mf][1] = Asu[(R + 8) * 36 + kc];
                a[mf][2] = Asu[R * 36 + kc + 4];
                a[mf][3] = Asu[(R + 8) * 36 + kc + 4];
            }
#pragma unroll
            for (int nt = 0; nt < 8; nt++) {
                const int nc = wn + nt * 8 + grp;
                uint32_t b0 = Bsu[nc * 36 + kc];
                uint32_t b1 = Bsu[nc * 36 + kc + 4];
#pragma unroll
                for (int mf = 0; mf < 2; mf++)
                    MMA_F16(c[mf][nt], a[mf], b0, b1);
            }
        }
        __syncthreads();
    }

    const int m0 = bm + wm + grp;
    const int n0 = wn + 2 * qd;
    if (merged) {
        if (region < 2) {
            __half* Cp = (region == 0) ? Cq : Ck;
            const size_t hbase = (size_t)head * ((size_t)S_LEN * HD) + colb0;
#pragma unroll
            for (int mf = 0; mf < 2; mf++)
#pragma unroll
                for (int nt = 0; nt < 8; nt++) {
                    int m = m0 + mf * 16;
                    int ncol = n0 + nt * 8;
                    *(uint32_t*)&Cp[hbase + (size_t)m * HD + ncol] =
                        pack2(c[mf][nt][0], c[mf][nt][1]);
                    *(uint32_t*)&Cp[hbase + (size_t)(m + 8) * HD + ncol] =
                        pack2(c[mf][nt][2], c[mf][nt][3]);
                }
        } else {
            // V: transposed store [h][d][s]
            const size_t vbase = (size_t)head * ((size_t)HD * S_LEN);
#pragma unroll
            for (int mf = 0; mf < 2; mf++)
#pragma unroll
                for (int nt = 0; nt < 8; nt++) {
                    int m = m0 + mf * 16;
                    int d = colb0 + n0 + nt * 8;
                    Cvt[vbase + (size_t)d * S_LEN + m]           = __float2half_rn(c[mf][nt][0]);
                    Cvt[vbase + (size_t)(d + 1) * S_LEN + m]     = __float2half_rn(c[mf][nt][1]);
                    Cvt[vbase + (size_t)d * S_LEN + m + 8]       = __float2half_rn(c[mf][nt][2]);
                    Cvt[vbase + (size_t)(d + 1) * S_LEN + m + 8] = __float2half_rn(c[mf][nt][3]);
                }
        }
    } else {
#pragma unroll
        for (int mf = 0; mf < 2; mf++)
#pragma unroll
            for (int nt = 0; nt < 8; nt++) {
                int m = m0 + mf * 16;
                int n = bn + n0 + nt * 8;
                *(float2*)&Cplain[(size_t)m * 2048 + n] =
                    make_float2(c[mf][nt][0], c[mf][nt][1]);
                *(float2*)&Cplain[(size_t)(m + 8) * 2048 + n] =
                    make_float2(c[mf][nt][2], c[mf][nt][3]);
            }
    }
}

// ---------------------------------------------------------------------------
// RoPE on fp16 q/k: one thread per (s, i); cos/sin once (fp64 range
// reduction), applied to 12 heads. Folds SCALING=0.0625 into q.
// position_ids int32/int64 auto-detected via word[1].
// ---------------------------------------------------------------------------
__global__ void rope_kernel(const void* __restrict__ pos_raw)
{
    int idx = blockIdx.x * blockDim.x + threadIdx.x;
    if (idx >= S_LEN * 128) return;
    int i = idx & 127;
    int s = idx >> 7;

    const int* p32 = (const int*)pos_raw;
    long long pll = (p32[1] == 0) ? ((const long long*)pos_raw)[s]
                                  : (long long)p32[s];
    float p = (float)pll;

    double invd = exp(-(double)i * (9.210340371976184 / 128.0));
    float f = (float)((double)p * invd);
    const double TWO_PI = 6.283185307179586476925287;
    double r = (double)f;
    r -= TWO_PI * floor(r / TWO_PI);
    float sv = sinf((float)r);
    float cv = cosf((float)r);

#pragma unroll
    for (int h = 0; h < NH; h++) {
        __half* base = g_q + ((size_t)h * S_LEN + s) * HD;
        float x1 = __half2float(base[i]), x2 = __half2float(base[i + 128]);
        base[i]       = __float2half_rn((x1 * cv - x2 * sv) * 0.0625f);
        base[i + 128] = __float2half_rn((x2 * cv + x1 * sv) * 0.0625f);
    }
#pragma unroll
    for (int h = 0; h < NKV; h++) {
        __half* base = g_k + ((size_t)h * S_LEN + s) * HD;
        float x1 = __half2float(base[i]), x2 = __half2float(base[i + 128]);
        base[i]       = __float2half_rn(x1 * cv - x2 * sv);
        base[i + 128] = __float2half_rn(x2 * cv + x1 * sv);
    }
}

// ---------------------------------------------------------------------------
// fp16 tensor-core flash attention with tanh softcap. Grid (16 pairs, 8
// heads) = 128 blocks (single wave). Block handles q-tiles qt and 31-qt
// (128 rows each) -> uniform 66 k-blocks (64 rows). 8 warps (4m x 2n).
// QK: warp 32q x 32k; PV: warp 32q x 128d. Softmax SIMT fp32: thread
// (ty,tx) owns rows ty*8..+7, cols tx*4..+3. P stored fp16. V pre-transposed.
// ---------------------------------------------------------------------------
#define AQ_STR 132                        // uint32 per Q/K row
#define AOFF_Q 0
#define AOFF_K (AOFF_Q + 128 * 528)       // 67584
#define AOFF_V (AOFF_K + 64 * 528)        // 101376
#define AOFF_S (AOFF_V + 256 * 144)       // 138240
#define AOFF_P (AOFF_S + 128 * 272)       // 173056
#define AOFF_R (AOFF_P + 128 * 144)       // 191488
#define AOFF_L (AOFF_R + 512)             // 192000
#define ATTN_SMEM (AOFF_L + 512)          // 192512

__global__ __launch_bounds__(256) void attn_h_kernel()
{
    extern __shared__ char smn[];
    const uint32_t sb = cvta_shared(smn);
    const uint32_t* Qfu = (const uint32_t*)(smn + AOFF_Q);
    const uint32_t* Kfu = (const uint32_t*)(smn + AOFF_K);
    const uint32_t* Vtu = (const uint32_t*)(smn + AOFF_V);
    float*    Ss  = (float*)(smn + AOFF_S);
    uint32_t* Ppu = (uint32_t*)(smn + AOFF_P);
    float*    rs  = (float*)(smn + AOFF_R);
    float*    li  = (float*)(smn + AOFF_L);

    const int h  = blockIdx.y;
    const int hk = h >> 1;
    const int tid  = threadIdx.x;
    const int lane = tid & 31;
    const int wid  = tid >> 5;
    const int wm   = (wid & 3) * 32;
    const int wc   = wid >> 2;
    const int grp  = lane >> 2;
    const int qd   = lane & 3;
    const int ty   = tid >> 4;
    const int tx   = tid & 15;

    const __half* Qh  = g_q  + (size_t)h  * S_LEN * HD;
    const __half* Kh  = g_k  + (size_t)hk * S_LEN * HD;
    const __half* Vth = g_vt + (size_t)hk * HD * S_LEN;

    const float LOG2E = 1.4426950408889634f;

    for (int half = 0; half < 2; half++) {
        const int qt = half ? (31 - blockIdx.x) : blockIdx.x;
        const int q0 = qt * 128;

        __syncthreads();
        // stage Q (128 x 256 halves)
#pragma unroll
        for (int p = 0; p < 16; p++) {
            int idx = tid + p * 256;
            int row = idx >> 5, cc = idx & 31;
            cp16(sb + AOFF_Q + row * 528 + cc * 16,
                 &Qh[(size_t)(q0 + row) * HD + cc * 8]);
        }
        CP_COMMIT();

        float mm[8], l[8], o[2][16][4];
#pragma unroll
        for (int r = 0; r < 8; r++) { mm[r] = -3.0e38f; l[r] = 0.f; }
#pragma unroll
        for (int mf = 0; mf < 2; mf++)
#pragma unroll
            for (int nt = 0; nt < 16; nt++)
#pragma unroll
                for (int r = 0; r < 4; r++) o[mf][nt][r] = 0.f;

        const int nkb = 2 * qt + 2;
        for (int kb = 0; kb < nkb; kb++) {
            const int k0 = kb * 64;
            __syncthreads();
            // K tile 64x256 halves
#pragma unroll
            for (int p = 0; p < 8; p++) {
                int idx = tid + p * 256;
                int row = idx >> 5, cc = idx & 31;
                cp16(sb + AOFF_K + row * 528 + cc * 16,
                     &Kh[(size_t)(k0 + row) * HD + cc * 8]);
            }
            CP_COMMIT();
            // Vt tile 256(d) x 64(s) halves
#pragma unroll
            for (int p = 0; p < 8; p++) {
                int idx = tid + p * 256;
                int row = idx >> 3, cc = idx & 7;
                cp16(sb + AOFF_V + row * 144 + cc * 16,
                     &Vth[(size_t)row * S_LEN + k0 + cc * 8]);
            }
            CP_COMMIT();
            CP_WAIT1();        // Q(first)/K ready, V may fly
            __syncthreads();

            // ---- QK: S[128][64] ----
            float s[2][4][4];
#pragma unroll
            for (int mf = 0; mf < 2; mf++)
#pragma unroll
                for (int nt = 0; nt < 4; nt++)
#pragma unroll
                    for (int r = 0; r < 4; r++) s[mf][nt][r] = 0.f;
#pragma unroll 4
            for (int ks = 0; ks < 16; ks++) {
                const int kc = ks * 8 + qd;
                uint32_t a[2][4];
#pragma unroll
                for (int mf = 0; mf < 2; mf++) {
                    const int R = wm + mf * 16 + grp;
                    a[mf][0] = Qfu[R * AQ_STR + kc];
                    a[mf][1] = Qfu[(R + 8) * AQ_STR + kc];
                    a[mf][2] = Qfu[R * AQ_STR + kc + 4];
                    a[mf][3] = Qfu[(R + 8) * AQ_STR + kc + 4];
                }
#pragma unroll
                for (int nt = 0; nt < 4; nt++) {
                    const int nc = wc * 32 + nt * 8 + grp;
                    uint32_t b0 = Kfu[nc * AQ_STR + kc];
                    uint32_t b1 = Kfu[nc * AQ_STR + kc + 4];
#pragma unroll
                    for (int mf = 0; mf < 2; mf++)
                        MMA_F16(s[mf][nt], a[mf], b0, b1);
                }
            }
#pragma unroll
            for (int mf = 0; mf < 2; mf++) {
                const int R = wm + mf * 16 + grp;
#pragma unroll
                for (int nt = 0; nt < 4; nt++) {
                    int col = wc * 32 + nt * 8 + 2 * qd;
                    *(float2*)&Ss[R * 68 + col] = make_float2(s[mf][nt][0], s[mf][nt][1]);
                    *(float2*)&Ss[(R + 8) * 68 + col] = make_float2(s[mf][nt][2], s[mf][nt][3]);
                }
            }
            CP_WAIT0();        // V ready
            __syncthreads();   // publish Ss

            // ---- softcap + causal + online softmax ----
#pragma unroll
            for (int r = 0; r < 8; r++) {
                const int row = ty * 8 + r;
                const int qrow = q0 + row;
                float4 raw = *(float4*)&Ss[row * 68 + tx * 4];
                float svv[4] = {raw.x, raw.y, raw.z, raw.w};
#pragma unroll
                for (int cc = 0; cc < 4; cc++) {
                    float x = svv[cc];
                    float u = x * 0.02f;
                    float u2 = u * u;
                    float val = x * (1.f + u2 * (-0.333333333f +
                                  u2 * (0.133333333f + u2 * -0.053968254f)));
                    if (u2 > 0.1225f) val = 50.f * tanhf(u);
                    int kcol = k0 + tx * 4 + cc;
                    if (kcol > qrow) val = -1.0e30f;
                    svv[cc] = val;
                }
                float mx = fmaxf(fmaxf(svv[0], svv[1]), fmaxf(svv[2], svv[3]));
#pragma unroll
                for (int off = 1; off < 16; off <<= 1)
                    mx = fmaxf(mx, __shfl_xor_sync(0xffffffffu, mx, off));
                float mn = fmaxf(mm[r], mx);
                float rescale = exp2f((mm[r] - mn) * LOG2E);
                float e0 = exp2f((svv[0] - mn) * LOG2E);
                float e1 = exp2f((svv[1] - mn) * LOG2E);
                float e2 = exp2f((svv[2] - mn) * LOG2E);
                float e3 = exp2f((svv[3] - mn) * LOG2E);
                uint32_t p01 = pack2(e0, e1);
                uint32_t p23 = pack2(e2, e3);
                Ppu[row * 36 + tx * 2]     = p01;
                Ppu[row * 36 + tx * 2 + 1] = p23;
                __half2 h01 = *(__half2*)&p01;
                __half2 h23 = *(__half2*)&p23;
                float psum = (__low2float(h01) + __high2float(h01)) +
                             (__low2float(h23) + __high2float(h23));
#pragma unroll
                for (int off = 1; off < 16; off <<= 1)
                    psum += __shfl_xor_sync(0xffffffffu, psum, off);
                l[r] = l[r] * rescale + psum;
                mm[r] = mn;
                if (tx == 0) rs[row] = rescale;
            }
            __syncthreads();

            // ---- rescale O, then PV ----
#pragma unroll
            for (int mf = 0; mf < 2; mf++) {
                const int R = wm + mf * 16 + grp;
                float rc0 = rs[R], rc1 = rs[R + 8];
#pragma unroll
                for (int nt = 0; nt < 16; nt++) {
                    o[mf][nt][0] *= rc0; o[mf][nt][1] *= rc0;
                    o[mf][nt][2] *= rc1; o[mf][nt][3] *= rc1;
                }
            }
#pragma unroll
            for (int s4 = 0; s4 < 4; s4++) {
                const int kc = s4 * 8 + qd;
                uint32_t a[2][4];
#pragma unroll
                for (int mf = 0; mf < 2; mf++) {
                    const int R = wm + mf * 16 + grp;
                    a[mf][0] = Ppu[R * 36 + kc];
                    a[mf][1] = Ppu[(R + 8) * 36 + kc];
                    a[mf][2] = Ppu[R * 36 + kc + 4];
                    a[mf][3] = Ppu[(R + 8) * 36 + kc + 4];
                }
#pragma unroll
                for (int nt = 0; nt < 16; nt++) {
                    const int nc = wc * 128 + nt * 8 + grp;
                    uint32_t b0 = Vtu[nc * 36 + kc];
                    uint32_t b1 = Vtu[nc * 36 + kc + 4];
#pragma unroll
                    for (int mf = 0; mf < 2; mf++)
                        MMA_F16(o[mf][nt], a[mf], b0, b1);
                }
            }
        }

        // ---- epilogue: normalize, write fp32 [s][h*HD+d] ----
        if (tx == 0) {
#pragma unroll
            for (int r = 0; r < 8; r++) li[ty * 8 + r] = 1.f / l[r];
        }
        __syncthreads();
#pragma unroll
        for (int mf = 0; mf < 2; mf++) {
            const int R = wm + mf * 16 + grp;
            float i0 = li[R], i1 = li[R + 8];
#pragma unroll
            for (int nt = 0; nt < 16; nt++) {
                int col = h * HD + wc * 128 + nt * 8 + 2 * qd;
                *(float2*)&g_attn[(size_t)(q0 + R) * 2048 + col] =
                    make_float2(o[mf][nt][0] * i0, o[mf][nt][1] * i0);
                *(float2*)&g_attn[(size_t)(q0 + R + 8) * 2048 + col] =
                    make_float2(o[mf][nt][2] * i1, o[mf][nt][3] * i1);
            }
        }
    }
}

// ---------------------------------------------------------------------------
extern "C" void kernel_launch(void* const* d_in, const int* in_sizes, int n_in,
                              void* d_out, int out_size)
{
    const float* hs  = (const float*)d_in[0];
    // d_in[1] = attention_mask: pure causal (window >= S), recomputed in-kernel
    const void*  pos = d_in[2];
    const float* wq  = (const float*)d_in[3];
    const float* wk  = (const float*)d_in[4];
    const float* wv  = (const float*)d_in[5];
    const float* wo  = (const float*)d_in[6];
    float* out = (float*)d_out;

    __half *pq, *pk, *pvt, *pah, *pwqt, *pwkt, *pwvt, *pwot;
    float *pa;
    cudaGetSymbolAddress((void**)&pq,   g_q);
    cudaGetSymbolAddress((void**)&pk,   g_k);
    cudaGetSymbolAddress((void**)&pvt,  g_vt);
    cudaGetSymbolAddress((void**)&pa,   g_attn);
    cudaGetSymbolAddress((void**)&pah,  g_ah);
    cudaGetSymbolAddress((void**)&pwqt, g_wqt);
    cudaGetSymbolAddress((void**)&pwkt, g_wkt);
    cudaGetSymbolAddress((void**)&pwvt, g_wvt);
    cudaGetSymbolAddress((void**)&pwot, g_wot);

    cudaFuncSetAttribute(gemm_h_kernel,
                         cudaFuncAttributeMaxDynamicSharedMemorySize, GH_SMEM);
    cudaFuncSetAttribute(attn_h_kernel,
                         cudaFuncAttributeMaxDynamicSharedMemorySize, ATTN_SMEM);

    const int n8 = (S_LEN * 2048) / 8;
    dim3 tb(32, 8);

    // prepasses: convert activations, transpose+convert weights
    tohalf_kernel<<<(n8 + 255) / 256, 256>>>(hs, pah, n8);
    thalf_kernel<<<dim3(64, 64), tb>>>(wq, pwqt, 2048);
    thalf_kernel<<<dim3(32, 64), tb>>>(wk, pwkt, 1024);
    thalf_kernel<<<dim3(32, 64), tb>>>(wv, pwvt, 1024);
    thalf_kernel<<<dim3(64, 64), tb>>>(wo, pwot, 2048);

    // fused QKV projection (fp16 HMMA)
    gemm_h_kernel<<<dim3(32, 32), 256, GH_SMEM>>>(
        pah, pwqt, pwkt, pwvt, pq, pk, pvt, nullptr, 1);
    // RoPE (+ fold attention scaling into q)
    rope_kernel<<<(S_LEN * 128) / 256, 256>>>(pos);
    // causal flash attention with tanh softcap (fp16 HMMA, single wave)
    attn_h_kernel<<<dim3(16, NH), 256, ATTN_SMEM>>>();
    // output projection
    tohalf_kernel<<<(n8 + 255) / 256, 256>>>(pa, pah, n8);
    gemm_h_kernel<<<dim3(16, 32), 256, GH_SMEM>>>(
        pah, pwot, nullptr, nullptr, nullptr, nullptr, nullptr, out, 0);
}

// round 10
// speedup vs baseline: 4.3519x; 1.0831x over previous
#include <cuda_runtime.h>
#include <cuda_fp16.h>
#include <math.h>
#include <stdint.h>

#define S_LEN 4096
#define NH 8
#define NKV 4
#define HD 256

// ---------------- scratch (allocation-free device globals) -----------------
__device__ __half g_q[(size_t)NH * S_LEN * HD];     // [h][s][d] fp16
__device__ __half g_k[(size_t)NKV * S_LEN * HD];    // [h][s][d] fp16
__device__ __half g_vt[(size_t)NKV * HD * S_LEN];   // [h][d][s] fp16 (transposed)
__device__ __half g_attn[(size_t)S_LEN * 2048];     // [s][h*HD+d] fp16
__device__ __half g_ah[(size_t)S_LEN * 2048];       // hs fp16
__device__ __half g_wqt[(size_t)2048 * 2048];       // weights [N][K] fp16
__device__ __half g_wkt[(size_t)1024 * 2048];
__device__ __half g_wvt[(size_t)1024 * 2048];
__device__ __half g_wot[(size_t)2048 * 2048];

__device__ __forceinline__ uint32_t cvta_shared(const void* p) {
    uint32_t a;
    asm("{ .reg .u64 t; cvta.to.shared.u64 t, %1; cvt.u32.u64 %0, t; }"
        : "=r"(a) : "l"(p));
    return a;
}

__device__ __forceinline__ void cp16(uint32_t dst, const void* src) {
    asm volatile("cp.async.cg.shared.global [%0], [%1], 16;"
                 :: "r"(dst), "l"(src));
}
#define CP_COMMIT() asm volatile("cp.async.commit_group;")
#define CP_WAIT0()  asm volatile("cp.async.wait_group 0;")
#define CP_WAIT1()  asm volatile("cp.async.wait_group 1;")

#define MMA_F16(C, A, B0, B1)                                               \
    asm volatile(                                                           \
        "mma.sync.aligned.m16n8k16.row.col.f32.f16.f16.f32 "                \
        "{%0,%1,%2,%3}, {%4,%5,%6,%7}, {%8,%9}, {%0,%1,%2,%3};"             \
        : "+f"((C)[0]), "+f"((C)[1]), "+f"((C)[2]), "+f"((C)[3])            \
        : "r"((A)[0]), "r"((A)[1]), "r"((A)[2]), "r"((A)[3]),               \
          "r"(B0), "r"(B1))

__device__ __forceinline__ uint32_t pack2(float a, float b) {
    __half2 h = __floats2half2_rn(a, b);
    return *(uint32_t*)&h;
}

// ---------------------------------------------------------------------------
// Prepass: fp32 -> fp16 (rn), 8 elems/thread.
// ---------------------------------------------------------------------------
__global__ void tohalf_kernel(const float* __restrict__ src,
                              __half* __restrict__ dst, int n8)
{
    int i = blockIdx.x * blockDim.x + threadIdx.x;
    if (i >= n8) return;
    float4 a = ((const float4*)src)[i * 2];
    float4 b = ((const float4*)src)[i * 2 + 1];
    uint4 o;
    o.x = pack2(a.x, a.y); o.y = pack2(a.z, a.w);
    o.z = pack2(b.x, b.y); o.w = pack2(b.z, b.w);
    ((uint4*)dst)[i] = o;
}

// ---------------------------------------------------------------------------
// Prepass: transpose + fp16 all four weights in ONE launch.
// blockIdx.x regions: [0,64) wq, [64,96) wk, [96,128) wv, [128,192) wo.
// ---------------------------------------------------------------------------
__global__ void thalf_all_kernel(const float* __restrict__ wq,
                                 const float* __restrict__ wk,
                                 const float* __restrict__ wv,
                                 const float* __restrict__ wo,
                                 __half* __restrict__ wqt,
                                 __half* __restrict__ wkt,
                                 __half* __restrict__ wvt,
                                 __half* __restrict__ wot)
{
    __shared__ float t[32][33];
    const int bx = blockIdx.x;
    const float* W;
    __half* Wt;
    int N, n0;
    if (bx < 64)       { W = wq; Wt = wqt; N = 2048; n0 = bx * 32; }
    else if (bx < 96)  { W = wk; Wt = wkt; N = 1024; n0 = (bx - 64) * 32; }
    else if (bx < 128) { W = wv; Wt = wvt; N = 1024; n0 = (bx - 96) * 32; }
    else               { W = wo; Wt = wot; N = 2048; n0 = (bx - 128) * 32; }
    const int k0 = blockIdx.y * 32;
    const int tx = threadIdx.x, ty = threadIdx.y;
#pragma unroll
    for (int j = 0; j < 4; j++)
        t[ty + 8 * j][tx] = W[(size_t)(k0 + ty + 8 * j) * N + n0 + tx];
    __syncthreads();
    const int nl = ty * 4 + (tx >> 3);
    const int kl = (tx & 7) * 4;
    uint2 o;
    o.x = pack2(t[kl + 0][nl], t[kl + 1][nl]);
    o.y = pack2(t[kl + 2][nl], t[kl + 3][nl]);
    *(uint2*)&Wt[(size_t)(n0 + nl) * 2048 + k0 + kl] = o;
}

// ---------------------------------------------------------------------------
// fp16 tensor-core GEMM: C[M,N] = A[M,2048] @ Wt[N,2048]^T, m16n8k16,
// 128x128 CTA tile, BK=64, 8 warps (4m x 2n), cp.async double-buffered.
// merged=1: fused QKV. bn<2048 -> q; <3072 -> k; else v transposed [h][d][s].
// merged=0: plain fp32 out [M,2048].
// ---------------------------------------------------------------------------
#define GH_PLANE 18432                   // 128 rows * 144 B
#define GH_STAGE (2 * GH_PLANE)
#define GH_SMEM  (2 * GH_STAGE)          // 73728 B

__global__ __launch_bounds__(256, 2) void gemm_h_kernel(
    const __half* __restrict__ A,
    const __half* __restrict__ B0t, const __half* __restrict__ B1t,
    const __half* __restrict__ B2t,
    __half* __restrict__ Cq, __half* __restrict__ Ck, __half* __restrict__ Cvt,
    float* __restrict__ Cplain, int merged)
{
    extern __shared__ char gsm[];
    const uint32_t smem_base = cvta_shared(gsm);

    const int tid  = threadIdx.x;
    const int lane = tid & 31;
    const int wid  = tid >> 5;
    const int wm   = (wid & 3) * 32;
    const int wn   = (wid >> 2) * 64;
    const int bm   = blockIdx.y * 128;
    const int bn   = blockIdx.x * 128;
    const int grp  = lane >> 2;
    const int qd   = lane & 3;

    const __half* Bt;
    int nb, head = 0, colb0 = 0, region = 0;
    if (merged) {
        if (bn < 2048)      { Bt = B0t; nb = bn;        region = 0; }
        else if (bn < 3072) { Bt = B1t; nb = bn - 2048; region = 1; }
        else                { Bt = B2t; nb = bn - 3072; region = 2; }
        head = nb >> 8;
        colb0 = nb & 255;
    } else {
        Bt = B0t; nb = bn;
    }

    auto load_stage = [&](int chunk, int st) {
        const int k0 = chunk * 64;
        const uint32_t sb = smem_base + st * GH_STAGE;
#pragma unroll
        for (int p = 0; p < 4; p++) {
            int idx = tid + p * 256;
            int row = idx >> 3, c = idx & 7;
            cp16(sb + row * 144 + c * 16,
                 &A[(size_t)(bm + row) * 2048 + k0 + c * 8]);
            cp16(sb + GH_PLANE + row * 144 + c * 16,
                 &Bt[(size_t)(nb + row) * 2048 + k0 + c * 8]);
        }
        CP_COMMIT();
    };

    float c[2][8][4];
#pragma unroll
    for (int mf = 0; mf < 2; mf++)
#pragma unroll
        for (int nt = 0; nt < 8; nt++)
#pragma unroll
            for (int r = 0; r < 4; r++) c[mf][nt][r] = 0.f;

    load_stage(0, 0);

    for (int i = 0; i < 32; i++) {
        const int st = i & 1;
        CP_WAIT0();
        __syncthreads();
        if (i + 1 < 32) load_stage(i + 1, st ^ 1);

        const uint32_t* Asu = (const uint32_t*)(gsm + st * GH_STAGE);
        const uint32_t* Bsu = (const uint32_t*)(gsm + st * GH_STAGE + GH_PLANE);
#pragma unroll
        for (int s = 0; s < 4; s++) {
            const int kc = s * 8 + qd;
            uint32_t a[2][4];
#pragma unroll
            for (int mf = 0; mf < 2; mf++) {
                const int R = wm + mf * 16 + grp;
                a[mf][0] = Asu[R * 36 + kc];
                a[mf][1] = Asu[(R + 8) * 36 + kc];
                a[mf][2] = Asu[R * 36 + kc + 4];
                a[mf][3] = Asu[(R + 8) * 36 + kc + 4];
            }
#pragma unroll
            for (int nt = 0; nt < 8; nt++) {
                const int nc = wn + nt * 8 + grp;
                uint32_t b0 = Bsu[nc * 36 + kc];
                uint32_t b1 = Bsu[nc * 36 + kc + 4];
#pragma unroll
                for (int mf = 0; mf < 2; mf++)
                    MMA_F16(c[mf][nt], a[mf], b0, b1);
            }
        }
        __syncthreads();
    }

    const int m0 = bm + wm + grp;
    const int n0 = wn + 2 * qd;
    if (merged) {
        if (region < 2) {
            __half* Cp = (region == 0) ? Cq : Ck;
            const size_t hbase = (size_t)head * ((size_t)S_LEN * HD) + colb0;
#pragma unroll
            for (int mf = 0; mf < 2; mf++)
#pragma unroll
                for (int nt = 0; nt < 8; nt++) {
                    int m = m0 + mf * 16;
                    int ncol = n0 + nt * 8;
                    *(uint32_t*)&Cp[hbase + (size_t)m * HD + ncol] =
                        pack2(c[mf][nt][0], c[mf][nt][1]);
                    *(uint32_t*)&Cp[hbase + (size_t)(m + 8) * HD + ncol] =
                        pack2(c[mf][nt][2], c[mf][nt][3]);
                }
        } else {
            const size_t vbase = (size_t)head * ((size_t)HD * S_LEN);
#pragma unroll
            for (int mf = 0; mf < 2; mf++)
#pragma unroll
                for (int nt = 0; nt < 8; nt++) {
                    int m = m0 + mf * 16;
                    int d = colb0 + n0 + nt * 8;
                    Cvt[vbase + (size_t)d * S_LEN + m]           = __float2half_rn(c[mf][nt][0]);
                    Cvt[vbase + (size_t)(d + 1) * S_LEN + m]     = __float2half_rn(c[mf][nt][1]);
                    Cvt[vbase + (size_t)d * S_LEN + m + 8]       = __float2half_rn(c[mf][nt][2]);
                    Cvt[vbase + (size_t)(d + 1) * S_LEN + m + 8] = __float2half_rn(c[mf][nt][3]);
                }
        }
    } else {
#pragma unroll
        for (int mf = 0; mf < 2; mf++)
#pragma unroll
            for (int nt = 0; nt < 8; nt++) {
                int m = m0 + mf * 16;
                int n = bn + n0 + nt * 8;
                *(float2*)&Cplain[(size_t)m * 2048 + n] =
                    make_float2(c[mf][nt][0], c[mf][nt][1]);
                *(float2*)&Cplain[(size_t)(m + 8) * 2048 + n] =
                    make_float2(c[mf][nt][2], c[mf][nt][3]);
            }
    }
}

// ---------------------------------------------------------------------------
// RoPE on fp16 q/k (fp64 range reduction; scaling folded into q).
// ---------------------------------------------------------------------------
__global__ void rope_kernel(const void* __restrict__ pos_raw)
{
    int idx = blockIdx.x * blockDim.x + threadIdx.x;
    if (idx >= S_LEN * 128) return;
    int i = idx & 127;
    int s = idx >> 7;

    const int* p32 = (const int*)pos_raw;
    long long pll = (p32[1] == 0) ? ((const long long*)pos_raw)[s]
                                  : (long long)p32[s];
    float p = (float)pll;

    double invd = exp(-(double)i * (9.210340371976184 / 128.0));
    float f = (float)((double)p * invd);
    const double TWO_PI = 6.283185307179586476925287;
    double r = (double)f;
    r -= TWO_PI * floor(r / TWO_PI);
    float sv = sinf((float)r);
    float cv = cosf((float)r);

#pragma unroll
    for (int h = 0; h < NH; h++) {
        __half* base = g_q + ((size_t)h * S_LEN + s) * HD;
        float x1 = __half2float(base[i]), x2 = __half2float(base[i + 128]);
        base[i]       = __float2half_rn((x1 * cv - x2 * sv) * 0.0625f);
        base[i + 128] = __float2half_rn((x2 * cv + x1 * sv) * 0.0625f);
    }
#pragma unroll
    for (int h = 0; h < NKV; h++) {
        __half* base = g_k + ((size_t)h * S_LEN + s) * HD;
        float x1 = __half2float(base[i]), x2 = __half2float(base[i + 128]);
        base[i]       = __float2half_rn(x1 * cv - x2 * sv);
        base[i + 128] = __float2half_rn(x2 * cv + x1 * sv);
    }
}

// ---------------------------------------------------------------------------
// fp16 flash attention, in-register softmax on QK fragments.
// Grid (16, 8) = 128 blocks, block = q-tiles qt & 31-qt (128 rows each),
// 66 uniform k-blocks of 64. 8 warps (4m x 2 k/d-half).
// Warp's QK frags cover rows wm..+32, k-cols wc*32..+32; row max/sum via
// quad shuffles; cross-warp m combined via 1KB smem partials (m exact &
// shared, l kept per-warp, combined at epilogue). P fp16 -> smem -> PV.
// Output written fp16 (feeds O-proj directly).
// ---------------------------------------------------------------------------
#define AQ_STR 132                        // uint32 per Q/K row
#define AOFF_Q 0
#define AOFF_K (128 * 528)                // 67584
#define AOFF_V (AOFF_K + 64 * 528)        // 101376
#define AOFF_P (AOFF_V + 256 * 144)       // 138240
#define AOFF_M (AOFF_P + 128 * 144)       // 156672  hm[128][2]
#define AOFF_L (AOFF_M + 1024)            // 157696  ll[128][2]
#define ATTN_SMEM (AOFF_L + 1024)         // 158720

__global__ __launch_bounds__(256) void attn_h_kernel()
{
    extern __shared__ char smn[];
    const uint32_t sb = cvta_shared(smn);
    const uint32_t* Qfu = (const uint32_t*)(smn + AOFF_Q);
    const uint32_t* Kfu = (const uint32_t*)(smn + AOFF_K);
    const uint32_t* Vtu = (const uint32_t*)(smn + AOFF_V);
    uint32_t* Ppu = (uint32_t*)(smn + AOFF_P);
    float* hm = (float*)(smn + AOFF_M);
    float* ll = (float*)(smn + AOFF_L);

    const int h  = blockIdx.y;
    const int hk = h >> 1;
    const int tid  = threadIdx.x;
    const int lane = tid & 31;
    const int wid  = tid >> 5;
    const int wm   = (wid & 3) * 32;
    const int wc   = wid >> 2;
    const int grp  = lane >> 2;
    const int qd   = lane & 3;

    const __half* Qh  = g_q  + (size_t)h  * S_LEN * HD;
    const __half* Kh  = g_k  + (size_t)hk * S_LEN * HD;
    const __half* Vth = g_vt + (size_t)hk * HD * S_LEN;

    const float LOG2E = 1.4426950408889634f;
    // row for slot (sl = mf*2 + rh): wm + (sl>>1)*16 + grp + (sl&1)*8
    int rowsl[4];
#pragma unroll
    for (int sl = 0; sl < 4; sl++)
        rowsl[sl] = wm + (sl >> 1) * 16 + grp + (sl & 1) * 8;

    for (int half = 0; half < 2; half++) {
        const int qt = half ? (31 - blockIdx.x) : blockIdx.x;
        const int q0 = qt * 128;

        __syncthreads();
        // stage Q (128 x 256 halves)
#pragma unroll
        for (int p = 0; p < 16; p++) {
            int idx = tid + p * 256;
            int row = idx >> 5, cc = idx & 31;
            cp16(sb + AOFF_Q + row * 528 + cc * 16,
                 &Qh[(size_t)(q0 + row) * HD + cc * 8]);
        }
        CP_COMMIT();

        float m_run[4], l_run[4], o[2][16][4];
#pragma unroll
        for (int sl = 0; sl < 4; sl++) { m_run[sl] = -3.0e38f; l_run[sl] = 0.f; }
#pragma unroll
        for (int mf = 0; mf < 2; mf++)
#pragma unroll
            for (int nt = 0; nt < 16; nt++)
#pragma unroll
                for (int r = 0; r < 4; r++) o[mf][nt][r] = 0.f;

        const int nkb = 2 * qt + 2;
        for (int kb = 0; kb < nkb; kb++) {
            const int k0 = kb * 64;
            __syncthreads();   // guard smem reuse (K/V/P/hm)
            // K tile 64x256 halves
#pragma unroll
            for (int p = 0; p < 8; p++) {
                int idx = tid + p * 256;
                int row = idx >> 5, cc = idx & 31;
                cp16(sb + AOFF_K + row * 528 + cc * 16,
                     &Kh[(size_t)(k0 + row) * HD + cc * 8]);
            }
            CP_COMMIT();
            // Vt tile 256(d) x 64(s) halves
#pragma unroll
            for (int p = 0; p < 8; p++) {
                int idx = tid + p * 256;
                int row = idx >> 3, cc = idx & 7;
                cp16(sb + AOFF_V + row * 144 + cc * 16,
                     &Vth[(size_t)row * S_LEN + k0 + cc * 8]);
            }
            CP_COMMIT();
            CP_WAIT1();        // Q(first)/K ready
            __syncthreads();

            // ---- QK: warp rows wm..+32, cols wc*32..+32 ----
            float s[2][4][4];
#pragma unroll
            for (int mf = 0; mf < 2; mf++)
#pragma unroll
                for (int nt = 0; nt < 4; nt++)
#pragma unroll
                    for (int r = 0; r < 4; r++) s[mf][nt][r] = 0.f;
#pragma unroll 4
            for (int ks = 0; ks < 16; ks++) {
                const int kc = ks * 8 + qd;
                uint32_t a[2][4];
#pragma unroll
                for (int mf = 0; mf < 2; mf++) {
                    const int R = wm + mf * 16 + grp;
                    a[mf][0] = Qfu[R * AQ_STR + kc];
                    a[mf][1] = Qfu[(R + 8) * AQ_STR + kc];
                    a[mf][2] = Qfu[R * AQ_STR + kc + 4];
                    a[mf][3] = Qfu[(R + 8) * AQ_STR + kc + 4];
                }
#pragma unroll
                for (int nt = 0; nt < 4; nt++) {
                    const int nc = wc * 32 + nt * 8 + grp;
                    uint32_t b0 = Kfu[nc * AQ_STR + kc];
                    uint32_t b1 = Kfu[nc * AQ_STR + kc + 4];
#pragma unroll
                    for (int mf = 0; mf < 2; mf++)
                        MMA_F16(s[mf][nt], a[mf], b0, b1);
                }
            }

            // ---- softcap + causal + local row max (in registers) ----
            float lm[4] = {-3.0e38f, -3.0e38f, -3.0e38f, -3.0e38f};
#pragma unroll
            for (int mf = 0; mf < 2; mf++)
#pragma unroll
                for (int nt = 0; nt < 4; nt++)
#pragma unroll
                    for (int cc = 0; cc < 4; cc++) {
                        float x = s[mf][nt][cc];
                        float u = x * 0.02f;
                        float u2 = u * u;
                        float val = x * (1.f + u2 * (-0.333333333f +
                                      u2 * (0.133333333f + u2 * -0.053968254f)));
                        if (u2 > 0.1225f) val = 50.f * tanhf(u);
                        int kcol = k0 + wc * 32 + nt * 8 + 2 * qd + (cc & 1);
                        int qrow = q0 + wm + mf * 16 + grp + (cc >> 1) * 8;
                        if (kcol > qrow) val = -1.0e30f;
                        s[mf][nt][cc] = val;
                        int sl = mf * 2 + (cc >> 1);
                        lm[sl] = fmaxf(lm[sl], val);
                    }
#pragma unroll
            for (int sl = 0; sl < 4; sl++) {
                lm[sl] = fmaxf(lm[sl], __shfl_xor_sync(0xffffffffu, lm[sl], 1));
                lm[sl] = fmaxf(lm[sl], __shfl_xor_sync(0xffffffffu, lm[sl], 2));
            }
            if (qd == 0) {
#pragma unroll
                for (int sl = 0; sl < 4; sl++)
                    hm[rowsl[sl] * 2 + wc] = lm[sl];
            }
            __syncthreads();   // hm partials visible

            // ---- combine max across the two k-half warps; exp; P ----
            float resc[4], ps[4];
#pragma unroll
            for (int sl = 0; sl < 4; sl++) {
                float om = fmaxf(hm[rowsl[sl] * 2], hm[rowsl[sl] * 2 + 1]);
                float mn = fmaxf(m_run[sl], om);
                resc[sl] = exp2f((m_run[sl] - mn) * LOG2E);
                m_run[sl] = mn;
                ps[sl] = 0.f;
            }
#pragma unroll
            for (int mf = 0; mf < 2; mf++) {
                const int sa = mf * 2, sb2 = mf * 2 + 1;
                const int R = wm + mf * 16 + grp;
#pragma unroll
                for (int nt = 0; nt < 4; nt++) {
                    float e0 = exp2f((s[mf][nt][0] - m_run[sa]) * LOG2E);
                    float e1 = exp2f((s[mf][nt][1] - m_run[sa]) * LOG2E);
                    float e2 = exp2f((s[mf][nt][2] - m_run[sb2]) * LOG2E);
                    float e3 = exp2f((s[mf][nt][3] - m_run[sb2]) * LOG2E);
                    ps[sa]  += e0 + e1;
                    ps[sb2] += e2 + e3;
                    Ppu[R * 36 + wc * 16 + nt * 4 + qd]       = pack2(e0, e1);
                    Ppu[(R + 8) * 36 + wc * 16 + nt * 4 + qd] = pack2(e2, e3);
                }
            }
#pragma unroll
            for (int sl = 0; sl < 4; sl++) {
                ps[sl] += __shfl_xor_sync(0xffffffffu, ps[sl], 1);
                ps[sl] += __shfl_xor_sync(0xffffffffu, ps[sl], 2);
                l_run[sl] = l_run[sl] * resc[sl] + ps[sl];
            }
            // rescale O by resc (rows: c0/c1 -> sl=mf*2, c2/c3 -> mf*2+1)
#pragma unroll
            for (int mf = 0; mf < 2; mf++) {
                float r0 = resc[mf * 2], r1 = resc[mf * 2 + 1];
#pragma unroll
                for (int nt = 0; nt < 16; nt++) {
                    o[mf][nt][0] *= r0; o[mf][nt][1] *= r0;
                    o[mf][nt][2] *= r1; o[mf][nt][3] *= r1;
                }
            }
            CP_WAIT0();        // V ready
            __syncthreads();   // P + V visible

            // ---- PV: warp rows wm..+32, d-cols wc*128..+128 ----
#pragma unroll
            for (int s4 = 0; s4 < 4; s4++) {
                const int kc = s4 * 8 + qd;
                uint32_t a[2][4];
#pragma unroll
                for (int mf = 0; mf < 2; mf++) {
                    const int R = wm + mf * 16 + grp;
                    a[mf][0] = Ppu[R * 36 + kc];
                    a[mf][1] = Ppu[(R + 8) * 36 + kc];
                    a[mf][2] = Ppu[R * 36 + kc + 4];
                    a[mf][3] = Ppu[(R + 8) * 36 + kc + 4];
                }
#pragma unroll
                for (int nt = 0; nt < 16; nt++) {
                    const int nc = wc * 128 + nt * 8 + grp;
                    uint32_t b0 = Vtu[nc * 36 + kc];
                    uint32_t b1 = Vtu[nc * 36 + kc + 4];
#pragma unroll
                    for (int mf = 0; mf < 2; mf++)
                        MMA_F16(o[mf][nt], a[mf], b0, b1);
                }
            }
        }

        // ---- epilogue: combine l halves, normalize, write fp16 ----
        if (qd == 0) {
#pragma unroll
            for (int sl = 0; sl < 4; sl++)
                ll[rowsl[sl] * 2 + wc] = l_run[sl];
        }
        __syncthreads();
        float li[4];
#pragma unroll
        for (int sl = 0; sl < 4; sl++)
            li[sl] = 1.f / (ll[rowsl[sl] * 2] + ll[rowsl[sl] * 2 + 1]);
#pragma unroll
        for (int mf = 0; mf < 2; mf++) {
            const int R = wm + mf * 16 + grp;
            float i0 = li[mf * 2], i1 = li[mf * 2 + 1];
#pragma unroll
            for (int nt = 0; nt < 16; nt++) {
                int col = h * HD + wc * 128 + nt * 8 + 2 * qd;
                *(uint32_t*)&g_attn[(size_t)(q0 + R) * 2048 + col] =
                    pack2(o[mf][nt][0] * i0, o[mf][nt][1] * i0);
                *(uint32_t*)&g_attn[(size_t)(q0 + R + 8) * 2048 + col] =
                    pack2(o[mf][nt][2] * i1, o[mf][nt][3] * i1);
            }
        }
    }
}

// ---------------------------------------------------------------------------
extern "C" void kernel_launch(void* const* d_in, const int* in_sizes, int n_in,
                              void* d_out, int out_size)
{
    const float* hs  = (const float*)d_in[0];
    // d_in[1] = attention_mask: pure causal (window >= S), recomputed in-kernel
    const void*  pos = d_in[2];
    const float* wq  = (const float*)d_in[3];
    const float* wk  = (const float*)d_in[4];
    const float* wv  = (const float*)d_in[5];
    const float* wo  = (const float*)d_in[6];
    float* out = (float*)d_out;

    __half *pq, *pk, *pvt, *pa, *pah, *pwqt, *pwkt, *pwvt, *pwot;
    cudaGetSymbolAddress((void**)&pq,   g_q);
    cudaGetSymbolAddress((void**)&pk,   g_k);
    cudaGetSymbolAddress((void**)&pvt,  g_vt);
    cudaGetSymbolAddress((void**)&pa,   g_attn);
    cudaGetSymbolAddress((void**)&pah,  g_ah);
    cudaGetSymbolAddress((void**)&pwqt, g_wqt);
    cudaGetSymbolAddress((void**)&pwkt, g_wkt);
    cudaGetSymbolAddress((void**)&pwvt, g_wvt);
    cudaGetSymbolAddress((void**)&pwot, g_wot);

    cudaFuncSetAttribute(gemm_h_kernel,
                         cudaFuncAttributeMaxDynamicSharedMemorySize, GH_SMEM);
    cudaFuncSetAttribute(attn_h_kernel,
                         cudaFuncAttributeMaxDynamicSharedMemorySize, ATTN_SMEM);

    const int n8 = (S_LEN * 2048) / 8;
    dim3 tb(32, 8);

    // prepasses
    tohalf_kernel<<<(n8 + 255) / 256, 256>>>(hs, pah, n8);
    thalf_all_kernel<<<dim3(192, 64), tb>>>(wq, wk, wv, wo,
                                            pwqt, pwkt, pwvt, pwot);
    // fused QKV projection
    gemm_h_kernel<<<dim3(32, 32), 256, GH_SMEM>>>(
        pah, pwqt, pwkt, pwvt, pq, pk, pvt, nullptr, 1);
    // RoPE (+ fold attention scaling into q)
    rope_kernel<<<(S_LEN * 128) / 256, 256>>>(pos);
    // causal flash attention with tanh softcap (fp16 out)
    attn_h_kernel<<<dim3(16, NH), 256, ATTN_SMEM>>>();
    // output projection (reads fp16 attention output directly)
    gemm_h_kernel<<<dim3(16, 32), 256, GH_SMEM>>>(
        pa, pwot, nullptr, nullptr, nullptr, nullptr, nullptr, out, 0);
}